// round 15
// baseline (speedup 1.0000x reference)
#include <cuda_runtime.h>
#include <cuda_fp16.h>
#include <mma.h>

using namespace nvcuda;

#define E_EDGES 1600000
#define NN 100000
#define HID 64
#define BN_EPS 1e-5f
#define INV_E (1.0f/1600000.0f)
#define NBLK 98   // ceil(NN/1024)
#define NEG_INF_BITS 0xFF800000
#define TILE_E 128
#define NTILES 12500          // tiles of 128 edges
#define MMA_GRID 152
#define MMA_THREADS 512

typedef unsigned long long ull;
typedef unsigned int uint;

__device__ __forceinline__ ull pack2(float lo, float hi){
  ull r; asm("mov.b64 %0,{%1,%2};" : "=l"(r) : "f"(lo), "f"(hi)); return r;
}
__device__ __forceinline__ void unpack2(ull v, float &lo, float &hi){
  asm("mov.b64 {%0,%1},%2;" : "=f"(lo), "=f"(hi) : "l"(v));
}
__device__ __forceinline__ ull fma2(ull a, ull b, ull c){
  ull d; asm("fma.rn.f32x2 %0,%1,%2,%3;" : "=l"(d) : "l"(a), "l"(b), "l"(c)); return d;
}
__device__ __forceinline__ uint smem_u32(const void* p){
  uint a; asm("{ .reg .u64 t; cvta.to.shared.u64 t, %1; cvt.u32.u64 %0, t; }" : "=r"(a) : "l"(p));
  return a;
}
__device__ __forceinline__ void cp_async16(uint saddr, const void* gptr){
  asm volatile("cp.async.cg.shared.global [%0], [%1], 16;" :: "r"(saddr), "l"(gptr));
}
#define CP_COMMIT() asm volatile("cp.async.commit_group;" ::: "memory")
#define CP_WAIT0()  asm volatile("cp.async.wait_group 0;" ::: "memory")

// ---------------- scratch (device globals; no allocations allowed) ----------------
__device__ __half d_h1[(size_t)E_EDGES*HID];   // permuted by dst (CSR order)
__device__ __half d_h2[(size_t)E_EDGES*HID];   // permuted by dst
__device__ int d_src[E_EDGES], d_dst[E_EDGES];
__device__ int d_node[E_EDGES];                // node id per permuted row
__device__ float d_sum0[HID], d_sq0[HID];
__device__ float d_sum1[HID], d_sq1[HID];
__device__ float d_sum2[HID], d_sq2[HID];
__device__ float d_normsq;
__device__ int d_is64;
__device__ float d_W2f[HID*HID], d_b2f[HID];
__device__ float d_W3f[HID*HID], d_b3f[HID];
__device__ float d_a3[HID], d_c3[HID];
__device__ int d_cnt[NN], d_off[NN+1], d_cur[NN];
__device__ int d_blk[128];

// ---------------- init: zero counters/stats, poison out with -inf ------------------
__global__ void k_init(int* __restrict__ outi){
  int i = blockIdx.x*blockDim.x + threadIdx.x;
  int stride = gridDim.x*blockDim.x;
  for (int j=i; j<NN*HID; j+=stride) outi[j] = NEG_INF_BITS;
  for (int j=i; j<NN; j+=stride) d_cnt[j]=0;
  if (i < HID){
    d_sum0[i]=0.f; d_sq0[i]=0.f;
    d_sum1[i]=0.f; d_sq1[i]=0.f;
    d_sum2[i]=0.f; d_sq2[i]=0.f;
  }
  if (i==0){ d_normsq = 0.f; d_is64 = 1; }
}

// ---------------- dtype probe: int64 vs int32 edge_index ---------------------------
__global__ void k_detect(const long long* __restrict__ ei){
  int tid = blockIdx.x*blockDim.x + threadIdx.x;
  int bad = 0;
  #pragma unroll 4
  for (int i = tid; i < (1<<20); i += gridDim.x*blockDim.x){
    long long v = ei[i];
    if (v < 0 || v >= NN) bad = 1;
  }
  if (__syncthreads_or(bad)){
    if (threadIdx.x == 0) d_is64 = 0;
  }
}

// ---------------- convert indices + global norm + dst histogram --------------------
__global__ void k_cvt_norm_hist(const void* __restrict__ eiv, const float* __restrict__ pos){
  const long long* ei64 = (const long long*)eiv;
  const int*       ei32 = (const int*)eiv;
  const bool is64 = (d_is64 != 0);
  int tid = blockIdx.x*blockDim.x + threadIdx.x;
  int stride = gridDim.x*blockDim.x;
  float local = 0.f;
  for (int e = tid; e < E_EDGES; e += stride){
    int s, d;
    if (is64){ s = (int)ei64[e]; d = (int)ei64[E_EDGES + e]; }
    else     { s = ei32[e];      d = ei32[E_EDGES + e]; }
    d_src[e] = s; d_dst[e] = d;
    float dx = pos[3*s+0] - pos[3*d+0];
    float dy = pos[3*s+1] - pos[3*d+1];
    float dz = pos[3*s+2] - pos[3*d+2];
    local += dx*dx + dy*dy + dz*dz;
    atomicAdd(&d_cnt[d], 1);
  }
  #pragma unroll
  for (int o=16;o>0;o>>=1) local += __shfl_down_sync(0xffffffffu, local, o);
  __shared__ float red[8];
  int lane = threadIdx.x & 31, wid = threadIdx.x >> 5;
  if (lane==0) red[wid]=local;
  __syncthreads();
  if (threadIdx.x==0){
    float s=0.f;
    #pragma unroll
    for (int i=0;i<8;i++) s+=red[i];
    atomicAdd(&d_normsq, s);
  }
}

// ---------------- parallel 3-phase exclusive scan ----------------------------------
__global__ void k_scan1(){
  __shared__ int wsum[32];
  int t = threadIdx.x, lane = t & 31, wid = t >> 5;
  int idx = blockIdx.x*1024 + t;
  int v = (idx < NN) ? d_cnt[idx] : 0;
  int x = v;
  #pragma unroll
  for (int o=1;o<32;o<<=1){ int y=__shfl_up_sync(0xffffffffu,x,o); if(lane>=o) x+=y; }
  if (lane==31) wsum[wid]=x;
  __syncthreads();
  if (wid==0){
    int y = wsum[lane];
    #pragma unroll
    for (int o=1;o<32;o<<=1){ int z=__shfl_up_sync(0xffffffffu,y,o); if(lane>=o) y+=z; }
    wsum[lane]=y;
  }
  __syncthreads();
  int excl = x - v + ((wid>0)? wsum[wid-1] : 0);
  if (idx < NN) d_off[idx] = excl;
  if (t==1023) d_blk[blockIdx.x] = wsum[31];
}

__global__ void k_scan2(){
  __shared__ int wsum[4];
  int t = threadIdx.x, lane = t & 31, wid = t >> 5;   // 128 threads
  int v = (t < NBLK) ? d_blk[t] : 0;
  int x = v;
  #pragma unroll
  for (int o=1;o<32;o<<=1){ int y=__shfl_up_sync(0xffffffffu,x,o); if(lane>=o) x+=y; }
  if (lane==31) wsum[wid]=x;
  __syncthreads();
  int woff = 0;
  for (int w=0; w<wid; w++) woff += wsum[w];
  if (t < NBLK) d_blk[t] = x - v + woff;
}

__global__ void k_scan3(){
  int idx = blockIdx.x*1024 + threadIdx.x;
  if (idx < NN){
    d_cur[idx] = d_off[idx] + d_blk[blockIdx.x];
  }
}

// ---------------- layer 1 (6->64) + fused CSR scatter, batched atomics --------------
__global__ void __launch_bounds__(256) k_layer1(const float* __restrict__ pos,
                         const float* __restrict__ x, const float* __restrict__ W1,
                         const float* __restrict__ b1){
  __shared__ int sp[256], ssn[256], sdn[256];
  __shared__ float ssum[64], ssq[64];
  const int t = threadIdx.x;
  const int lane = t & 31, w = t >> 5;
  float invn = rsqrtf(d_normsq);
  ull wp[6];
  #pragma unroll
  for (int k=0;k<6;k++){
    float2 wv = ((const float2*)(W1 + k*HID))[lane];
    wp[k] = pack2(wv.x, wv.y);
  }
  float2 bb = ((const float2*)b1)[lane];
  ull bias = pack2(bb.x, bb.y);

  // phase A: claim CSR slots
  {
    int e = blockIdx.x*256 + t;
    int s = d_src[e], d = d_dst[e];
    int p = atomicAdd(&d_cur[d], 1);
    d_node[p] = d;
    sp[t] = p; ssn[t] = s; sdn[t] = d;
  }
  if (t < 64){ ssum[t]=0.f; ssq[t]=0.f; }
  __syncthreads();

  // phase B: compute 32 edges per warp
  float sx=0.f, sy=0.f, qx=0.f, qy=0.f;
  #pragma unroll 4
  for (int j=0;j<32;j++){
    int idx = w*32 + j;
    int p = sp[idx], s = ssn[idx], d = sdn[idx];
    float i0 = (pos[3*s+0]-pos[3*d+0])*invn;
    float i1 = (pos[3*s+1]-pos[3*d+1])*invn;
    float i2 = (pos[3*s+2]-pos[3*d+2])*invn;
    float i3 = x[3*d+0], i4 = x[3*d+1], i5 = x[3*d+2];
    ull acc = bias;
    acc = fma2(pack2(i0,i0), wp[0], acc);
    acc = fma2(pack2(i1,i1), wp[1], acc);
    acc = fma2(pack2(i2,i2), wp[2], acc);
    acc = fma2(pack2(i3,i3), wp[3], acc);
    acc = fma2(pack2(i4,i4), wp[4], acc);
    acc = fma2(pack2(i5,i5), wp[5], acc);
    float h0, h1v; unpack2(acc, h0, h1v);
    h0 = fmaxf(h0, 0.f); h1v = fmaxf(h1v, 0.f);
    ((__half2*)(d_h1 + (size_t)p*HID))[lane] = __floats2half2_rn(h0, h1v);
    sx += h0; sy += h1v; qx += h0*h0; qy += h1v*h1v;
  }
  // smem-reduced stats flush
  atomicAdd(&ssum[2*lane+0], sx);
  atomicAdd(&ssum[2*lane+1], sy);
  atomicAdd(&ssq [2*lane+0], qx);
  atomicAdd(&ssq [2*lane+1], qy);
  __syncthreads();
  if (t < 64){
    atomicAdd(&d_sum0[t], ssum[t]);
    atomicAdd(&d_sq0[t], ssq[t]);
  }
}

// ---------------- fold BN(prev layer) into next layer's weights -------------------
__global__ void k_fold(const float* __restrict__ W, const float* __restrict__ b,
                       const float* __restrict__ g, const float* __restrict__ be, int which){
  __shared__ float a[HID], c[HID];
  int t = threadIdx.x;
  const float* sum = (which==0) ? d_sum0 : d_sum1;
  const float* sq  = (which==0) ? d_sq0  : d_sq1;
  float* Wf = (which==0) ? d_W2f : d_W3f;
  float* bf = (which==0) ? d_b2f : d_b3f;
  float mu = sum[t]*INV_E;
  float var = sq[t]*INV_E - mu*mu;
  float av = g[t]*rsqrtf(var + BN_EPS);
  a[t] = av; c[t] = be[t] - av*mu;
  __syncthreads();
  float cb = 0.f;
  for (int k=0;k<HID;k++){
    float w = W[k*HID + t];
    Wf[k*HID + t] = a[k]*w;
    cb += c[k]*w;
  }
  bf[t] = b[t] + cb;
}

__global__ void k_affine3(const float* __restrict__ g, const float* __restrict__ be){
  int t = threadIdx.x;
  float mu = d_sum2[t]*INV_E;
  float var = d_sq2[t]*INV_E - mu*mu;
  float av = g[t]*rsqrtf(var + BN_EPS);
  d_a3[t] = av; d_c3[t] = be[t] - av*mu;
}

// ---------------- layers 2/3 on WMMA + cp.async double-buffer, 128-edge tiles ------
// which==0: h1 -> h2 (store fp16, stats to d_sum1/d_sq1)
// which==1: h2 -> segmented max into outi (stats to d_sum2/d_sq2)
// 512 threads = 16 warps. Tile = 128 edges. Warp (eg = w>>1 in 0..7, nh = w&1)
// computes edges [eg*16,..+16) x channels [nh*32,..+32). B fragments register-
// resident (loaded once); A tile double-buffered via cp.async.
__global__ void __launch_bounds__(MMA_THREADS) k_layer_mma(int which, int* __restrict__ outi){
  const __half* __restrict__ hin = (which==0) ? d_h1 : d_h2;
  __half* __restrict__ hout = d_h2;
  const float* __restrict__ Wf = (which==0) ? d_W2f : d_W3f;
  const float* __restrict__ bf = (which==0) ? d_b2f : d_b3f;
  float* gs = (which==0) ? d_sum1 : d_sum2;
  float* gq = (which==0) ? d_sq1  : d_sq2;

  __shared__ __align__(32) __half Ash[2][TILE_E][72];  // 2 x 128 x 144B = 36864B
  __shared__ __align__(32) float stage[TILE_E][72];    // 36864B; also W prep scratch
  __shared__ float bsm[64];
  __shared__ int nsm[TILE_E];

  const int t = threadIdx.x;
  const int warp = t >> 5;
  const int eg = warp >> 1;      // edge group: rows [eg*16, eg*16+16)
  const int nh = warp & 1;       // channel half: cols [nh*32, nh*32+32)

  // ---- prep W in smem scratch as Wh[n*64+k] (=B[k][n] col-major, ld=64) ----------
  {
    __half* Wh = (__half*)stage;   // hi at [0,4096), lo at [4096,8192)
    for (int idx = t; idx < HID*HID; idx += MMA_THREADS){
      int k = idx >> 6, n = idx & 63;
      float w = Wf[k*HID + n];
      __half hi = __float2half_rn(w);
      __half lo = __float2half_rn(w - __half2float(hi));
      Wh[n*64 + k] = hi;
      Wh[4096 + n*64 + k] = lo;
    }
  }
  if (t < 64) bsm[t] = bf[t];
  __syncthreads();

  // ---- load B fragments once (col_major: B[k][n] = Wh[k + n*64]) ------------------
  wmma::fragment<wmma::matrix_b,16,16,16,__half,wmma::col_major> bh[2][4], bl[2][4];
  {
    const __half* Wh = (const __half*)stage;
    #pragma unroll
    for (int nt=0; nt<2; nt++){
      int n0 = nh*32 + nt*16;
      #pragma unroll
      for (int kk=0; kk<4; kk++){
        wmma::load_matrix_sync(bh[nt][kk], Wh + kk*16 + n0*64, 64);
        wmma::load_matrix_sync(bl[nt][kk], Wh + 4096 + kk*16 + n0*64, 64);
      }
    }
  }
  __syncthreads();   // stage scratch free for reuse

  const int e_ld = t >> 2, q_ld = t & 3;    // A-load role: 32B per thread, 128 rows
  const uint a_s0 = smem_u32(&Ash[0][e_ld][q_ld*16]);
  const uint a_s1 = smem_u32(&Ash[1][e_ld][q_ld*16]);

  // first prefetch into buffer 0
  {
    int tl = blockIdx.x;
    if (tl < NTILES){
      const __half* g = hin + ((size_t)tl*TILE_E + e_ld)*HID + q_ld*16;
      cp_async16(a_s0, g); cp_async16(a_s0 + 16, g + 8);
    }
    CP_COMMIT();
  }

  float sacc = 0.f, qacc = 0.f;   // per (ch = t&63, strip = t>>6): 16 edges each
  const int ch = t & 63, strip = t >> 6;   // strip in 0..7
  int buf = 0;

  for (int tile = blockIdx.x; tile < NTILES; tile += gridDim.x){
    size_t e0 = (size_t)tile * TILE_E;

    CP_WAIT0();
    if (which==1 && t < TILE_E) nsm[t] = d_node[e0 + t];
    __syncthreads();    // A tile (buf) + nsm ready

    // ---- prefetch NEXT tile into the other buffer (overlaps mma + epilogue) --------
    {
      int nxt = tile + gridDim.x;
      if (nxt < NTILES){
        const __half* g = hin + ((size_t)nxt*TILE_E + e_ld)*HID + q_ld*16;
        uint sa = buf ? a_s0 : a_s1;
        cp_async16(sa, g); cp_async16(sa + 16, g + 8);
      }
      CP_COMMIT();
    }

    // ---- wmma mainloop: acc[nt] += A_kk * (Whi + Wlo) -------------------------------
    wmma::fragment<wmma::accumulator,16,16,16,float> acc[2];
    wmma::fill_fragment(acc[0], 0.f);
    wmma::fill_fragment(acc[1], 0.f);
    #pragma unroll
    for (int kk=0; kk<4; kk++){
      wmma::fragment<wmma::matrix_a,16,16,16,__half,wmma::row_major> af;
      wmma::load_matrix_sync(af, &Ash[buf][eg*16][kk*16], 72);
      #pragma unroll
      for (int nt=0; nt<2; nt++){
        wmma::mma_sync(acc[nt], af, bh[nt][kk], acc[nt]);
        wmma::mma_sync(acc[nt], af, bl[nt][kk], acc[nt]);
      }
    }
    wmma::store_matrix_sync(&stage[eg*16][nh*32 +  0], acc[0], 72, wmma::mem_row_major);
    wmma::store_matrix_sync(&stage[eg*16][nh*32 + 16], acc[1], 72, wmma::mem_row_major);
    __syncthreads();

    // ---- bias + relu (in stats pass), stats, seg-max; writeback v for h2 store ------
    {
      float bias = bsm[ch];
      float ss=0.f, qq=0.f;
      if (which==0){
        #pragma unroll 4
        for (int e=strip*16; e<strip*16+16; e++){
          float v = fmaxf(stage[e][ch] + bias, 0.f);
          stage[e][ch] = v;
          ss += v; qq += v*v;
        }
      } else {
        int curn = -1; float cm = 0.f;
        #pragma unroll 4
        for (int e=strip*16; e<strip*16+16; e++){
          float v = fmaxf(stage[e][ch] + bias, 0.f);
          ss += v; qq += v*v;
          int n = nsm[e];
          if (n != curn){
            if (curn >= 0) atomicMax(&outi[(size_t)curn*HID + ch], __float_as_int(cm));
            curn = n; cm = v;
          } else {
            cm = fmaxf(cm, v);
          }
        }
        atomicMax(&outi[(size_t)curn*HID + ch], __float_as_int(cm));
      }
      sacc += ss; qacc += qq;
    }

    // ---- layer2: coalesced fp16 store of relu'd tile --------------------------------
    if (which==0){
      __syncthreads();
      const float* srow = &stage[e_ld][q_ld*16];
      uint4 o;
      __half2* hp = (__half2*)&o;
      #pragma unroll
      for (int j=0;j<4;j++) hp[j] = __floats2half2_rn(srow[2*j], srow[2*j+1]);
      uint4 o2;
      __half2* hp2 = (__half2*)&o2;
      #pragma unroll
      for (int j=0;j<4;j++) hp2[j] = __floats2half2_rn(srow[8+2*j], srow[8+2*j+1]);
      uint4* dst = (uint4*)(hout + (e0 + e_ld)*HID + q_ld*16);
      dst[0] = o; dst[1] = o2;
    }
    __syncthreads();
    buf ^= 1;
  }

  // flush per-channel stats (8 partials per channel per block)
  atomicAdd(&gs[ch], sacc);
  atomicAdd(&gq[ch], qacc);
}

// ---------------- finish: BN3 affine on maxes, zero for empty nodes ----------------
__global__ void k_finish(float* __restrict__ out){
  __shared__ float a[HID], c[HID];
  if (threadIdx.x < HID){ a[threadIdx.x] = d_a3[threadIdx.x]; c[threadIdx.x] = d_c3[threadIdx.x]; }
  __syncthreads();
  int idx = blockIdx.x*blockDim.x + threadIdx.x;
  int stride = gridDim.x*blockDim.x;
  for (int i = idx; i < NN*HID; i += stride){
    int ch = i & (HID-1);
    int bits = ((const int*)out)[i];
    float v = __int_as_float(bits);
    out[i] = (bits == (int)NEG_INF_BITS) ? 0.f : fmaf(a[ch], v, c[ch]);
  }
}

// ---------------- launch ------------------------------------------------------------
extern "C" void kernel_launch(void* const* d_in, const int* in_sizes, int n_in,
                              void* d_out, int out_size){
  const float*     x   = (const float*)d_in[0];
  const float*     pos = (const float*)d_in[1];
  const void*      ei  = d_in[2];
  const float* W1=(const float*)d_in[3];  const float* b1=(const float*)d_in[4];
  const float* g1=(const float*)d_in[5];  const float* be1=(const float*)d_in[6];
  const float* W2=(const float*)d_in[7];  const float* b2=(const float*)d_in[8];
  const float* g2=(const float*)d_in[9];  const float* be2=(const float*)d_in[10];
  const float* W3=(const float*)d_in[11]; const float* b3=(const float*)d_in[12];
  const float* g3=(const float*)d_in[13]; const float* be3=(const float*)d_in[14];
  float* out = (float*)d_out;
  (void)in_sizes; (void)n_in; (void)out_size;

  k_init<<<2048,256>>>((int*)out);
  k_detect<<<1024,256>>>((const long long*)ei);
  k_cvt_norm_hist<<<2048,256>>>(ei, pos);
  k_scan1<<<NBLK,1024>>>();
  k_scan2<<<1,128>>>();
  k_scan3<<<NBLK,1024>>>();
  k_layer1<<<6250,256>>>(pos, x, W1, b1);
  k_fold<<<1,64>>>(W2, b2, g1, be1, 0);
  k_layer_mma<<<MMA_GRID,MMA_THREADS>>>(0, (int*)out);
  k_fold<<<1,64>>>(W3, b3, g2, be2, 1);
  k_layer_mma<<<MMA_GRID,MMA_THREADS>>>(1, (int*)out);
  k_affine3<<<1,64>>>(g3, be3);
  k_finish<<<2048,256>>>(out);
}

// round 16
// speedup vs baseline: 1.0216x; 1.0216x over previous
#include <cuda_runtime.h>
#include <cuda_fp16.h>
#include <mma.h>

using namespace nvcuda;

#define E_EDGES 1600000
#define NN 100000
#define HID 64
#define BN_EPS 1e-5f
#define INV_E (1.0f/1600000.0f)
#define NBLK 98   // ceil(NN/1024)
#define NEG_INF_BITS 0xFF800000
#define NTILES 25000          // tiles of 64 edges
#define MMA_GRID 296

typedef unsigned long long ull;
typedef unsigned int uint;

__device__ __forceinline__ ull pack2(float lo, float hi){
  ull r; asm("mov.b64 %0,{%1,%2};" : "=l"(r) : "f"(lo), "f"(hi)); return r;
}
__device__ __forceinline__ void unpack2(ull v, float &lo, float &hi){
  asm("mov.b64 {%0,%1},%2;" : "=f"(lo), "=f"(hi) : "l"(v));
}
__device__ __forceinline__ ull fma2(ull a, ull b, ull c){
  ull d; asm("fma.rn.f32x2 %0,%1,%2,%3;" : "=l"(d) : "l"(a), "l"(b), "l"(c)); return d;
}
__device__ __forceinline__ uint smem_u32(const void* p){
  uint a; asm("{ .reg .u64 t; cvta.to.shared.u64 t, %1; cvt.u32.u64 %0, t; }" : "=r"(a) : "l"(p));
  return a;
}
__device__ __forceinline__ void cp_async16(uint saddr, const void* gptr){
  asm volatile("cp.async.cg.shared.global [%0], [%1], 16;" :: "r"(saddr), "l"(gptr));
}
#define CP_COMMIT() asm volatile("cp.async.commit_group;" ::: "memory")
#define CP_WAIT1()  asm volatile("cp.async.wait_group 1;" ::: "memory")

// ---------------- scratch (device globals; no allocations allowed) ----------------
__device__ __half d_h1[(size_t)E_EDGES*HID];   // permuted by dst (CSR order)
__device__ __half d_h2[(size_t)E_EDGES*HID];   // permuted by dst
__device__ int d_src[E_EDGES], d_dst[E_EDGES];
__device__ int d_node[E_EDGES];                // node id per permuted row
__device__ float d_sum0[HID], d_sq0[HID];
__device__ float d_sum1[HID], d_sq1[HID];
__device__ float d_sum2[HID], d_sq2[HID];
__device__ float d_normsq;
__device__ int d_is64;
__device__ float d_W2f[HID*HID], d_b2f[HID];
__device__ float d_W3f[HID*HID], d_b3f[HID];
__device__ float d_a3[HID], d_c3[HID];
__device__ int d_cnt[NN], d_off[NN+1], d_cur[NN];
__device__ int d_blk[128];

// ---------------- init: zero counters/stats, poison out with -inf ------------------
__global__ void k_init(int* __restrict__ outi){
  int i = blockIdx.x*blockDim.x + threadIdx.x;
  int stride = gridDim.x*blockDim.x;
  for (int j=i; j<NN*HID; j+=stride) outi[j] = NEG_INF_BITS;
  for (int j=i; j<NN; j+=stride) d_cnt[j]=0;
  if (i < HID){
    d_sum0[i]=0.f; d_sq0[i]=0.f;
    d_sum1[i]=0.f; d_sq1[i]=0.f;
    d_sum2[i]=0.f; d_sq2[i]=0.f;
  }
  if (i==0){ d_normsq = 0.f; d_is64 = 1; }
}

// ---------------- dtype probe: int64 vs int32 edge_index ---------------------------
__global__ void k_detect(const long long* __restrict__ ei){
  int tid = blockIdx.x*blockDim.x + threadIdx.x;
  int bad = 0;
  #pragma unroll 4
  for (int i = tid; i < (1<<20); i += gridDim.x*blockDim.x){
    long long v = ei[i];
    if (v < 0 || v >= NN) bad = 1;
  }
  if (__syncthreads_or(bad)){
    if (threadIdx.x == 0) d_is64 = 0;
  }
}

// ---------------- convert indices + global norm + dst histogram --------------------
__global__ void k_cvt_norm_hist(const void* __restrict__ eiv, const float* __restrict__ pos){
  const long long* ei64 = (const long long*)eiv;
  const int*       ei32 = (const int*)eiv;
  const bool is64 = (d_is64 != 0);
  int tid = blockIdx.x*blockDim.x + threadIdx.x;
  int stride = gridDim.x*blockDim.x;
  float local = 0.f;
  for (int e = tid; e < E_EDGES; e += stride){
    int s, d;
    if (is64){ s = (int)ei64[e]; d = (int)ei64[E_EDGES + e]; }
    else     { s = ei32[e];      d = ei32[E_EDGES + e]; }
    d_src[e] = s; d_dst[e] = d;
    float dx = pos[3*s+0] - pos[3*d+0];
    float dy = pos[3*s+1] - pos[3*d+1];
    float dz = pos[3*s+2] - pos[3*d+2];
    local += dx*dx + dy*dy + dz*dz;
    atomicAdd(&d_cnt[d], 1);
  }
  #pragma unroll
  for (int o=16;o>0;o>>=1) local += __shfl_down_sync(0xffffffffu, local, o);
  __shared__ float red[8];
  int lane = threadIdx.x & 31, wid = threadIdx.x >> 5;
  if (lane==0) red[wid]=local;
  __syncthreads();
  if (threadIdx.x==0){
    float s=0.f;
    #pragma unroll
    for (int i=0;i<8;i++) s+=red[i];
    atomicAdd(&d_normsq, s);
  }
}

// ---------------- parallel 3-phase exclusive scan ----------------------------------
__global__ void k_scan1(){
  __shared__ int wsum[32];
  int t = threadIdx.x, lane = t & 31, wid = t >> 5;
  int idx = blockIdx.x*1024 + t;
  int v = (idx < NN) ? d_cnt[idx] : 0;
  int x = v;
  #pragma unroll
  for (int o=1;o<32;o<<=1){ int y=__shfl_up_sync(0xffffffffu,x,o); if(lane>=o) x+=y; }
  if (lane==31) wsum[wid]=x;
  __syncthreads();
  if (wid==0){
    int y = wsum[lane];
    #pragma unroll
    for (int o=1;o<32;o<<=1){ int z=__shfl_up_sync(0xffffffffu,y,o); if(lane>=o) y+=z; }
    wsum[lane]=y;
  }
  __syncthreads();
  int excl = x - v + ((wid>0)? wsum[wid-1] : 0);
  if (idx < NN) d_off[idx] = excl;
  if (t==1023) d_blk[blockIdx.x] = wsum[31];
}

__global__ void k_scan2(){
  __shared__ int wsum[4];
  int t = threadIdx.x, lane = t & 31, wid = t >> 5;   // 128 threads
  int v = (t < NBLK) ? d_blk[t] : 0;
  int x = v;
  #pragma unroll
  for (int o=1;o<32;o<<=1){ int y=__shfl_up_sync(0xffffffffu,x,o); if(lane>=o) x+=y; }
  if (lane==31) wsum[wid]=x;
  __syncthreads();
  int woff = 0;
  for (int w=0; w<wid; w++) woff += wsum[w];
  if (t < NBLK) d_blk[t] = x - v + woff;
}

__global__ void k_scan3(){
  int idx = blockIdx.x*1024 + threadIdx.x;
  if (idx < NN){
    d_cur[idx] = d_off[idx] + d_blk[blockIdx.x];
  }
}

// ---------------- layer 1 (6->64) + fused CSR scatter, batched atomics --------------
__global__ void __launch_bounds__(256) k_layer1(const float* __restrict__ pos,
                         const float* __restrict__ x, const float* __restrict__ W1,
                         const float* __restrict__ b1){
  __shared__ int sp[256], ssn[256], sdn[256];
  __shared__ float ssum[64], ssq[64];
  const int t = threadIdx.x;
  const int lane = t & 31, w = t >> 5;
  float invn = rsqrtf(d_normsq);
  ull wp[6];
  #pragma unroll
  for (int k=0;k<6;k++){
    float2 wv = ((const float2*)(W1 + k*HID))[lane];
    wp[k] = pack2(wv.x, wv.y);
  }
  float2 bb = ((const float2*)b1)[lane];
  ull bias = pack2(bb.x, bb.y);

  // phase A: claim CSR slots
  {
    int e = blockIdx.x*256 + t;
    int s = d_src[e], d = d_dst[e];
    int p = atomicAdd(&d_cur[d], 1);
    d_node[p] = d;
    sp[t] = p; ssn[t] = s; sdn[t] = d;
  }
  if (t < 64){ ssum[t]=0.f; ssq[t]=0.f; }
  __syncthreads();

  // phase B: compute 32 edges per warp
  float sx=0.f, sy=0.f, qx=0.f, qy=0.f;
  #pragma unroll 4
  for (int j=0;j<32;j++){
    int idx = w*32 + j;
    int p = sp[idx], s = ssn[idx], d = sdn[idx];
    float i0 = (pos[3*s+0]-pos[3*d+0])*invn;
    float i1 = (pos[3*s+1]-pos[3*d+1])*invn;
    float i2 = (pos[3*s+2]-pos[3*d+2])*invn;
    float i3 = x[3*d+0], i4 = x[3*d+1], i5 = x[3*d+2];
    ull acc = bias;
    acc = fma2(pack2(i0,i0), wp[0], acc);
    acc = fma2(pack2(i1,i1), wp[1], acc);
    acc = fma2(pack2(i2,i2), wp[2], acc);
    acc = fma2(pack2(i3,i3), wp[3], acc);
    acc = fma2(pack2(i4,i4), wp[4], acc);
    acc = fma2(pack2(i5,i5), wp[5], acc);
    float h0, h1v; unpack2(acc, h0, h1v);
    h0 = fmaxf(h0, 0.f); h1v = fmaxf(h1v, 0.f);
    ((__half2*)(d_h1 + (size_t)p*HID))[lane] = __floats2half2_rn(h0, h1v);
    sx += h0; sy += h1v; qx += h0*h0; qy += h1v*h1v;
  }
  // smem-reduced stats flush
  atomicAdd(&ssum[2*lane+0], sx);
  atomicAdd(&ssum[2*lane+1], sy);
  atomicAdd(&ssq [2*lane+0], qx);
  atomicAdd(&ssq [2*lane+1], qy);
  __syncthreads();
  if (t < 64){
    atomicAdd(&d_sum0[t], ssum[t]);
    atomicAdd(&d_sq0[t], ssq[t]);
  }
}

// ---------------- fold BN(prev layer) into next layer's weights -------------------
__global__ void k_fold(const float* __restrict__ W, const float* __restrict__ b,
                       const float* __restrict__ g, const float* __restrict__ be, int which){
  __shared__ float a[HID], c[HID];
  int t = threadIdx.x;
  const float* sum = (which==0) ? d_sum0 : d_sum1;
  const float* sq  = (which==0) ? d_sq0  : d_sq1;
  float* Wf = (which==0) ? d_W2f : d_W3f;
  float* bf = (which==0) ? d_b2f : d_b3f;
  float mu = sum[t]*INV_E;
  float var = sq[t]*INV_E - mu*mu;
  float av = g[t]*rsqrtf(var + BN_EPS);
  a[t] = av; c[t] = be[t] - av*mu;
  __syncthreads();
  float cb = 0.f;
  for (int k=0;k<HID;k++){
    float w = W[k*HID + t];
    Wf[k*HID + t] = a[k]*w;
    cb += c[k]*w;
  }
  bf[t] = b[t] + cb;
}

__global__ void k_affine3(const float* __restrict__ g, const float* __restrict__ be){
  int t = threadIdx.x;
  float mu = d_sum2[t]*INV_E;
  float var = d_sq2[t]*INV_E - mu*mu;
  float av = g[t]*rsqrtf(var + BN_EPS);
  d_a3[t] = av; d_c3[t] = be[t] - av*mu;
}

// ---------------- layers 2/3 on WMMA + 3-deep cp.async pipeline --------------------
// which==0: h1 -> h2 (store fp16, stats to d_sum1/d_sq1)
// which==1: h2 -> segmented max into outi (stats to d_sum2/d_sq2)
// R14 structure (64-edge tiles, 256 threads, B fragments register-resident) with a
// 3-buffer cp.async ring: two tile-loads in flight (wait_group 1), giving each
// global load a two-tile window to complete.
__global__ void __launch_bounds__(256) k_layer_mma(int which, int* __restrict__ outi){
  const __half* __restrict__ hin = (which==0) ? d_h1 : d_h2;
  __half* __restrict__ hout = d_h2;
  const float* __restrict__ Wf = (which==0) ? d_W2f : d_W3f;
  const float* __restrict__ bf = (which==0) ? d_b2f : d_b3f;
  float* gs = (which==0) ? d_sum1 : d_sum2;
  float* gq = (which==0) ? d_sq1  : d_sq2;

  __shared__ __align__(32) __half Ash[3][64][72];  // 3-buffer A tile ring (27648B)
  __shared__ __align__(32) float stage[64][72];    // fp32 staging; also W prep scratch
  __shared__ float bsm[64];
  __shared__ int nsm[64];

  const int t = threadIdx.x;
  const int warp = t >> 5;
  const int eg = warp >> 1;      // edge group: rows [eg*16, eg*16+16)
  const int nh = warp & 1;       // channel half: cols [nh*32, nh*32+32)

  // ---- prep W in smem scratch as Wh[n*64+k] (=B[k][n] col-major, ld=64) ----------
  {
    __half* Wh = (__half*)stage;   // hi at [0,4096), lo at [4096,8192)
    for (int idx = t; idx < HID*HID; idx += 256){
      int k = idx >> 6, n = idx & 63;
      float w = Wf[k*HID + n];
      __half hi = __float2half_rn(w);
      __half lo = __float2half_rn(w - __half2float(hi));
      Wh[n*64 + k] = hi;
      Wh[4096 + n*64 + k] = lo;
    }
  }
  if (t < 64) bsm[t] = bf[t];
  __syncthreads();

  // ---- load B fragments once (col_major: B[k][n] = Wh[k + n*64]) ------------------
  wmma::fragment<wmma::matrix_b,16,16,16,__half,wmma::col_major> bh[2][4], bl[2][4];
  {
    const __half* Wh = (const __half*)stage;
    #pragma unroll
    for (int nt=0; nt<2; nt++){
      int n0 = nh*32 + nt*16;
      #pragma unroll
      for (int kk=0; kk<4; kk++){
        wmma::load_matrix_sync(bh[nt][kk], Wh + kk*16 + n0*64, 64);
        wmma::load_matrix_sync(bl[nt][kk], Wh + 4096 + kk*16 + n0*64, 64);
      }
    }
  }
  __syncthreads();   // stage scratch free for reuse

  const int e_ld = t >> 2, q_ld = t & 3;    // A-load role: 32B per thread
  uint a_sb[3];
  a_sb[0] = smem_u32(&Ash[0][e_ld][q_ld*16]);
  a_sb[1] = smem_u32(&Ash[1][e_ld][q_ld*16]);
  a_sb[2] = smem_u32(&Ash[2][e_ld][q_ld*16]);

  // prologue: prefetch tiles for iterations 0 and 1 (two groups in flight)
  {
    int tl0 = blockIdx.x;
    if (tl0 < NTILES){
      const __half* g = hin + ((size_t)tl0*64 + e_ld)*HID + q_ld*16;
      cp_async16(a_sb[0], g); cp_async16(a_sb[0] + 16, g + 8);
    }
    CP_COMMIT();
    int tl1 = blockIdx.x + gridDim.x;
    if (tl1 < NTILES){
      const __half* g = hin + ((size_t)tl1*64 + e_ld)*HID + q_ld*16;
      cp_async16(a_sb[1], g); cp_async16(a_sb[1] + 16, g + 8);
    }
    CP_COMMIT();
  }

  float sacc = 0.f, qacc = 0.f;   // per (ch = t&63, strip = t>>6): 16 edges each
  const int ch = t & 63, strip = t >> 6;
  int iter = 0;

  for (int tile = blockIdx.x; tile < NTILES; tile += gridDim.x, iter++){
    size_t e0 = (size_t)tile * 64;
    int buf = iter - (iter/3)*3;

    CP_WAIT1();          // oldest group (this tile) complete; next may still fly
    if (which==1 && t < 64) nsm[t] = d_node[e0 + t];
    __syncthreads();     // A tile (buf) + nsm ready

    // ---- prefetch tile iter+2 into buffer (iter+2)%3 --------------------------------
    {
      int nxt = tile + 2*gridDim.x;
      int nbuf = buf + 2; if (nbuf >= 3) nbuf -= 3;
      if (nxt < NTILES){
        const __half* g = hin + ((size_t)nxt*64 + e_ld)*HID + q_ld*16;
        cp_async16(a_sb[nbuf], g); cp_async16(a_sb[nbuf] + 16, g + 8);
      }
      CP_COMMIT();
    }

    // ---- wmma mainloop: acc[nt] += A_kk * (Whi + Wlo) -------------------------------
    wmma::fragment<wmma::accumulator,16,16,16,float> acc[2];
    wmma::fill_fragment(acc[0], 0.f);
    wmma::fill_fragment(acc[1], 0.f);
    #pragma unroll
    for (int kk=0; kk<4; kk++){
      wmma::fragment<wmma::matrix_a,16,16,16,__half,wmma::row_major> af;
      wmma::load_matrix_sync(af, &Ash[buf][eg*16][kk*16], 72);
      #pragma unroll
      for (int nt=0; nt<2; nt++){
        wmma::mma_sync(acc[nt], af, bh[nt][kk], acc[nt]);
        wmma::mma_sync(acc[nt], af, bl[nt][kk], acc[nt]);
      }
    }
    wmma::store_matrix_sync(&stage[eg*16][nh*32 +  0], acc[0], 72, wmma::mem_row_major);
    wmma::store_matrix_sync(&stage[eg*16][nh*32 + 16], acc[1], 72, wmma::mem_row_major);
    __syncthreads();

    // ---- bias + relu (in stats pass), stats, seg-max; writeback v for h2 store ------
    {
      float bias = bsm[ch];
      float ss=0.f, qq=0.f;
      if (which==0){
        #pragma unroll 4
        for (int e=strip*16; e<strip*16+16; e++){
          float v = fmaxf(stage[e][ch] + bias, 0.f);
          stage[e][ch] = v;
          ss += v; qq += v*v;
        }
      } else {
        int curn = -1; float cm = 0.f;
        #pragma unroll 4
        for (int e=strip*16; e<strip*16+16; e++){
          float v = fmaxf(stage[e][ch] + bias, 0.f);
          ss += v; qq += v*v;
          int n = nsm[e];
          if (n != curn){
            if (curn >= 0) atomicMax(&outi[(size_t)curn*HID + ch], __float_as_int(cm));
            curn = n; cm = v;
          } else {
            cm = fmaxf(cm, v);
          }
        }
        atomicMax(&outi[(size_t)curn*HID + ch], __float_as_int(cm));
      }
      sacc += ss; qacc += qq;
    }

    // ---- layer2: coalesced fp16 store of relu'd tile --------------------------------
    if (which==0){
      __syncthreads();
      const float* srow = &stage[e_ld][q_ld*16];
      uint4 o;
      __half2* hp = (__half2*)&o;
      #pragma unroll
      for (int j=0;j<4;j++) hp[j] = __floats2half2_rn(srow[2*j], srow[2*j+1]);
      uint4 o2;
      __half2* hp2 = (__half2*)&o2;
      #pragma unroll
      for (int j=0;j<4;j++) hp2[j] = __floats2half2_rn(srow[8+2*j], srow[8+2*j+1]);
      uint4* dst = (uint4*)(hout + (e0 + e_ld)*HID + q_ld*16);
      dst[0] = o; dst[1] = o2;
    }
    __syncthreads();
  }

  // flush per-channel stats (4 partials per channel per block)
  atomicAdd(&gs[ch], sacc);
  atomicAdd(&gq[ch], qacc);
}

// ---------------- finish: BN3 affine on maxes, zero for empty nodes ----------------
__global__ void k_finish(float* __restrict__ out){
  __shared__ float a[HID], c[HID];
  if (threadIdx.x < HID){ a[threadIdx.x] = d_a3[threadIdx.x]; c[threadIdx.x] = d_c3[threadIdx.x]; }
  __syncthreads();
  int idx = blockIdx.x*blockDim.x + threadIdx.x;
  int stride = gridDim.x*blockDim.x;
  for (int i = idx; i < NN*HID; i += stride){
    int ch = i & (HID-1);
    int bits = ((const int*)out)[i];
    float v = __int_as_float(bits);
    out[i] = (bits == (int)NEG_INF_BITS) ? 0.f : fmaf(a[ch], v, c[ch]);
  }
}

// ---------------- launch ------------------------------------------------------------
extern "C" void kernel_launch(void* const* d_in, const int* in_sizes, int n_in,
                              void* d_out, int out_size){
  const float*     x   = (const float*)d_in[0];
  const float*     pos = (const float*)d_in[1];
  const void*      ei  = d_in[2];
  const float* W1=(const float*)d_in[3];  const float* b1=(const float*)d_in[4];
  const float* g1=(const float*)d_in[5];  const float* be1=(const float*)d_in[6];
  const float* W2=(const float*)d_in[7];  const float* b2=(const float*)d_in[8];
  const float* g2=(const float*)d_in[9];  const float* be2=(const float*)d_in[10];
  const float* W3=(const float*)d_in[11]; const float* b3=(const float*)d_in[12];
  const float* g3=(const float*)d_in[13]; const float* be3=(const float*)d_in[14];
  float* out = (float*)d_out;
  (void)in_sizes; (void)n_in; (void)out_size;

  k_init<<<2048,256>>>((int*)out);
  k_detect<<<1024,256>>>((const long long*)ei);
  k_cvt_norm_hist<<<2048,256>>>(ei, pos);
  k_scan1<<<NBLK,1024>>>();
  k_scan2<<<1,128>>>();
  k_scan3<<<NBLK,1024>>>();
  k_layer1<<<6250,256>>>(pos, x, W1, b1);
  k_fold<<<1,64>>>(W2, b2, g1, be1, 0);
  k_layer_mma<<<MMA_GRID,256>>>(0, (int*)out);
  k_fold<<<1,64>>>(W3, b3, g2, be2, 1);
  k_layer_mma<<<MMA_GRID,256>>>(1, (int*)out);
  k_affine3<<<1,64>>>(g3, be3);
  k_finish<<<2048,256>>>(out);
}

// round 17
// speedup vs baseline: 1.1153x; 1.0917x over previous
#include <cuda_runtime.h>
#include <cuda_fp16.h>
#include <mma.h>

using namespace nvcuda;

#define E_EDGES 1600000
#define NN 100000
#define HID 64
#define BN_EPS 1e-5f
#define INV_E (1.0f/1600000.0f)
#define NBLK 98   // ceil(NN/1024)
#define NEG_INF_BITS 0xFF800000
#define NTILES 25000          // tiles of 64 edges
#define MMA_GRID 296

typedef unsigned long long ull;
typedef unsigned int uint;

__device__ __forceinline__ ull pack2(float lo, float hi){
  ull r; asm("mov.b64 %0,{%1,%2};" : "=l"(r) : "f"(lo), "f"(hi)); return r;
}
__device__ __forceinline__ void unpack2(ull v, float &lo, float &hi){
  asm("mov.b64 {%0,%1},%2;" : "=f"(lo), "=f"(hi) : "l"(v));
}
__device__ __forceinline__ ull fma2(ull a, ull b, ull c){
  ull d; asm("fma.rn.f32x2 %0,%1,%2,%3;" : "=l"(d) : "l"(a), "l"(b), "l"(c)); return d;
}
__device__ __forceinline__ uint smem_u32(const void* p){
  uint a; asm("{ .reg .u64 t; cvta.to.shared.u64 t, %1; cvt.u32.u64 %0, t; }" : "=r"(a) : "l"(p));
  return a;
}
__device__ __forceinline__ void cp_async16(uint saddr, const void* gptr){
  asm volatile("cp.async.cg.shared.global [%0], [%1], 16;" :: "r"(saddr), "l"(gptr));
}
#define CP_COMMIT() asm volatile("cp.async.commit_group;" ::: "memory")
#define CP_WAIT0()  asm volatile("cp.async.wait_group 0;" ::: "memory")

// ---------------- scratch (device globals; no allocations allowed) ----------------
__device__ __half d_h1[(size_t)E_EDGES*HID];   // permuted by dst (CSR order)
__device__ __half d_h2[(size_t)E_EDGES*HID];   // permuted by dst
__device__ int d_src[E_EDGES], d_dst[E_EDGES];
__device__ int d_node[E_EDGES];                // node id per permuted row
__device__ float d_sum0[HID], d_sq0[HID];
__device__ float d_sum1[HID], d_sq1[HID];
__device__ float d_sum2[HID], d_sq2[HID];
__device__ float d_normsq;
__device__ int d_is64;
__device__ float d_W2f[HID*HID], d_b2f[HID];
__device__ float d_W3f[HID*HID], d_b3f[HID];
__device__ float d_a3[HID], d_c3[HID];
__device__ int d_cnt[NN], d_off[NN+1], d_cur[NN];
__device__ int d_blk[128];

// ---------------- init: zero counters/stats, poison out with -inf ------------------
__global__ void k_init(int* __restrict__ outi){
  int i = blockIdx.x*blockDim.x + threadIdx.x;
  int stride = gridDim.x*blockDim.x;
  for (int j=i; j<NN*HID; j+=stride) outi[j] = NEG_INF_BITS;
  for (int j=i; j<NN; j+=stride) d_cnt[j]=0;
  if (i < HID){
    d_sum0[i]=0.f; d_sq0[i]=0.f;
    d_sum1[i]=0.f; d_sq1[i]=0.f;
    d_sum2[i]=0.f; d_sq2[i]=0.f;
  }
  if (i==0){ d_normsq = 0.f; d_is64 = 1; }
}

// ---------------- dtype probe: int64 vs int32 edge_index ---------------------------
__global__ void k_detect(const long long* __restrict__ ei){
  int tid = blockIdx.x*blockDim.x + threadIdx.x;
  int bad = 0;
  #pragma unroll 4
  for (int i = tid; i < (1<<20); i += gridDim.x*blockDim.x){
    long long v = ei[i];
    if (v < 0 || v >= NN) bad = 1;
  }
  if (__syncthreads_or(bad)){
    if (threadIdx.x == 0) d_is64 = 0;
  }
}

// ---------------- convert indices + global norm + dst histogram --------------------
__global__ void k_cvt_norm_hist(const void* __restrict__ eiv, const float* __restrict__ pos){
  const long long* ei64 = (const long long*)eiv;
  const int*       ei32 = (const int*)eiv;
  const bool is64 = (d_is64 != 0);
  int tid = blockIdx.x*blockDim.x + threadIdx.x;
  int stride = gridDim.x*blockDim.x;
  float local = 0.f;
  for (int e = tid; e < E_EDGES; e += stride){
    int s, d;
    if (is64){ s = (int)ei64[e]; d = (int)ei64[E_EDGES + e]; }
    else     { s = ei32[e];      d = ei32[E_EDGES + e]; }
    d_src[e] = s; d_dst[e] = d;
    float dx = pos[3*s+0] - pos[3*d+0];
    float dy = pos[3*s+1] - pos[3*d+1];
    float dz = pos[3*s+2] - pos[3*d+2];
    local += dx*dx + dy*dy + dz*dz;
    atomicAdd(&d_cnt[d], 1);
  }
  #pragma unroll
  for (int o=16;o>0;o>>=1) local += __shfl_down_sync(0xffffffffu, local, o);
  __shared__ float red[8];
  int lane = threadIdx.x & 31, wid = threadIdx.x >> 5;
  if (lane==0) red[wid]=local;
  __syncthreads();
  if (threadIdx.x==0){
    float s=0.f;
    #pragma unroll
    for (int i=0;i<8;i++) s+=red[i];
    atomicAdd(&d_normsq, s);
  }
}

// ---------------- parallel 3-phase exclusive scan ----------------------------------
__global__ void k_scan1(){
  __shared__ int wsum[32];
  int t = threadIdx.x, lane = t & 31, wid = t >> 5;
  int idx = blockIdx.x*1024 + t;
  int v = (idx < NN) ? d_cnt[idx] : 0;
  int x = v;
  #pragma unroll
  for (int o=1;o<32;o<<=1){ int y=__shfl_up_sync(0xffffffffu,x,o); if(lane>=o) x+=y; }
  if (lane==31) wsum[wid]=x;
  __syncthreads();
  if (wid==0){
    int y = wsum[lane];
    #pragma unroll
    for (int o=1;o<32;o<<=1){ int z=__shfl_up_sync(0xffffffffu,y,o); if(lane>=o) y+=z; }
    wsum[lane]=y;
  }
  __syncthreads();
  int excl = x - v + ((wid>0)? wsum[wid-1] : 0);
  if (idx < NN) d_off[idx] = excl;
  if (t==1023) d_blk[blockIdx.x] = wsum[31];
}

__global__ void k_scan2(){
  __shared__ int wsum[4];
  int t = threadIdx.x, lane = t & 31, wid = t >> 5;   // 128 threads
  int v = (t < NBLK) ? d_blk[t] : 0;
  int x = v;
  #pragma unroll
  for (int o=1;o<32;o<<=1){ int y=__shfl_up_sync(0xffffffffu,x,o); if(lane>=o) x+=y; }
  if (lane==31) wsum[wid]=x;
  __syncthreads();
  int woff = 0;
  for (int w=0; w<wid; w++) woff += wsum[w];
  if (t < NBLK) d_blk[t] = x - v + woff;
}

__global__ void k_scan3(){
  int idx = blockIdx.x*1024 + threadIdx.x;
  if (idx < NN){
    d_cur[idx] = d_off[idx] + d_blk[blockIdx.x];
  }
}

// ---------------- layer 1 (6->64) + fused CSR scatter, batched atomics --------------
__global__ void __launch_bounds__(256) k_layer1(const float* __restrict__ pos,
                         const float* __restrict__ x, const float* __restrict__ W1,
                         const float* __restrict__ b1){
  __shared__ int sp[256], ssn[256], sdn[256];
  __shared__ float ssum[64], ssq[64];
  const int t = threadIdx.x;
  const int lane = t & 31, w = t >> 5;
  float invn = rsqrtf(d_normsq);
  ull wp[6];
  #pragma unroll
  for (int k=0;k<6;k++){
    float2 wv = ((const float2*)(W1 + k*HID))[lane];
    wp[k] = pack2(wv.x, wv.y);
  }
  float2 bb = ((const float2*)b1)[lane];
  ull bias = pack2(bb.x, bb.y);

  // phase A: claim CSR slots
  {
    int e = blockIdx.x*256 + t;
    int s = d_src[e], d = d_dst[e];
    int p = atomicAdd(&d_cur[d], 1);
    d_node[p] = d;
    sp[t] = p; ssn[t] = s; sdn[t] = d;
  }
  if (t < 64){ ssum[t]=0.f; ssq[t]=0.f; }
  __syncthreads();

  // phase B: compute 32 edges per warp
  float sx=0.f, sy=0.f, qx=0.f, qy=0.f;
  #pragma unroll 4
  for (int j=0;j<32;j++){
    int idx = w*32 + j;
    int p = sp[idx], s = ssn[idx], d = sdn[idx];
    float i0 = (pos[3*s+0]-pos[3*d+0])*invn;
    float i1 = (pos[3*s+1]-pos[3*d+1])*invn;
    float i2 = (pos[3*s+2]-pos[3*d+2])*invn;
    float i3 = x[3*d+0], i4 = x[3*d+1], i5 = x[3*d+2];
    ull acc = bias;
    acc = fma2(pack2(i0,i0), wp[0], acc);
    acc = fma2(pack2(i1,i1), wp[1], acc);
    acc = fma2(pack2(i2,i2), wp[2], acc);
    acc = fma2(pack2(i3,i3), wp[3], acc);
    acc = fma2(pack2(i4,i4), wp[4], acc);
    acc = fma2(pack2(i5,i5), wp[5], acc);
    float h0, h1v; unpack2(acc, h0, h1v);
    h0 = fmaxf(h0, 0.f); h1v = fmaxf(h1v, 0.f);
    ((__half2*)(d_h1 + (size_t)p*HID))[lane] = __floats2half2_rn(h0, h1v);
    sx += h0; sy += h1v; qx += h0*h0; qy += h1v*h1v;
  }
  // smem-reduced stats flush
  atomicAdd(&ssum[2*lane+0], sx);
  atomicAdd(&ssum[2*lane+1], sy);
  atomicAdd(&ssq [2*lane+0], qx);
  atomicAdd(&ssq [2*lane+1], qy);
  __syncthreads();
  if (t < 64){
    atomicAdd(&d_sum0[t], ssum[t]);
    atomicAdd(&d_sq0[t], ssq[t]);
  }
}

// ---------------- fold BN(prev layer) into next layer's weights -------------------
__global__ void k_fold(const float* __restrict__ W, const float* __restrict__ b,
                       const float* __restrict__ g, const float* __restrict__ be, int which){
  __shared__ float a[HID], c[HID];
  int t = threadIdx.x;
  const float* sum = (which==0) ? d_sum0 : d_sum1;
  const float* sq  = (which==0) ? d_sq0  : d_sq1;
  float* Wf = (which==0) ? d_W2f : d_W3f;
  float* bf = (which==0) ? d_b2f : d_b3f;
  float mu = sum[t]*INV_E;
  float var = sq[t]*INV_E - mu*mu;
  float av = g[t]*rsqrtf(var + BN_EPS);
  a[t] = av; c[t] = be[t] - av*mu;
  __syncthreads();
  float cb = 0.f;
  for (int k=0;k<HID;k++){
    float w = W[k*HID + t];
    Wf[k*HID + t] = a[k]*w;
    cb += c[k]*w;
  }
  bf[t] = b[t] + cb;
}

__global__ void k_affine3(const float* __restrict__ g, const float* __restrict__ be){
  int t = threadIdx.x;
  float mu = d_sum2[t]*INV_E;
  float var = d_sq2[t]*INV_E - mu*mu;
  float av = g[t]*rsqrtf(var + BN_EPS);
  d_a3[t] = av; d_c3[t] = be[t] - av*mu;
}

// ---------------- layers 2/3 on WMMA + double-buffered cp.async --------------------
// which==0: h1 -> h2 (fused single-pass epilogue: bias/relu/stats/column fp16 store)
// which==1: h2 -> segmented max into outi (stats to d_sum2/d_sq2)
// R14 structure: 64-edge tiles, 256 threads, B fragments register-resident,
// 2-deep cp.async pipeline. Layer2 epilogue collapsed to ONE pass (no stage
// writeback, no separate store pass, one fewer barrier per tile).
__global__ void __launch_bounds__(256) k_layer_mma(int which, int* __restrict__ outi){
  const __half* __restrict__ hin = (which==0) ? d_h1 : d_h2;
  __half* __restrict__ hout = d_h2;
  const float* __restrict__ Wf = (which==0) ? d_W2f : d_W3f;
  const float* __restrict__ bf = (which==0) ? d_b2f : d_b3f;
  float* gs = (which==0) ? d_sum1 : d_sum2;
  float* gq = (which==0) ? d_sq1  : d_sq2;

  __shared__ __align__(32) __half Ash[2][64][72];  // double-buffered A tile
  __shared__ __align__(32) float stage[64][72];    // fp32 staging; also W prep scratch
  __shared__ float bsm[64];
  __shared__ int nsm[64];

  const int t = threadIdx.x;
  const int warp = t >> 5;
  const int eg = warp >> 1;      // edge group: rows [eg*16, eg*16+16)
  const int nh = warp & 1;       // channel half: cols [nh*32, nh*32+32)

  // ---- prep W in smem scratch as Wh[n*64+k] (=B[k][n] col-major, ld=64) ----------
  {
    __half* Wh = (__half*)stage;   // hi at [0,4096), lo at [4096,8192)
    for (int idx = t; idx < HID*HID; idx += 256){
      int k = idx >> 6, n = idx & 63;
      float w = Wf[k*HID + n];
      __half hi = __float2half_rn(w);
      __half lo = __float2half_rn(w - __half2float(hi));
      Wh[n*64 + k] = hi;
      Wh[4096 + n*64 + k] = lo;
    }
  }
  if (t < 64) bsm[t] = bf[t];
  __syncthreads();

  // ---- load B fragments once (col_major: B[k][n] = Wh[k + n*64]) ------------------
  wmma::fragment<wmma::matrix_b,16,16,16,__half,wmma::col_major> bh[2][4], bl[2][4];
  {
    const __half* Wh = (const __half*)stage;
    #pragma unroll
    for (int nt=0; nt<2; nt++){
      int n0 = nh*32 + nt*16;
      #pragma unroll
      for (int kk=0; kk<4; kk++){
        wmma::load_matrix_sync(bh[nt][kk], Wh + kk*16 + n0*64, 64);
        wmma::load_matrix_sync(bl[nt][kk], Wh + 4096 + kk*16 + n0*64, 64);
      }
    }
  }
  __syncthreads();   // stage scratch free for reuse

  const int e_ld = t >> 2, q_ld = t & 3;    // A-load role: 32B per thread
  const uint a_s0 = smem_u32(&Ash[0][e_ld][q_ld*16]);
  const uint a_s1 = smem_u32(&Ash[1][e_ld][q_ld*16]);

  // first prefetch into buffer 0
  {
    int tl = blockIdx.x;
    if (tl < NTILES){
      const __half* g = hin + ((size_t)tl*64 + e_ld)*HID + q_ld*16;
      cp_async16(a_s0, g); cp_async16(a_s0 + 16, g + 8);
    }
    CP_COMMIT();
  }

  float sacc = 0.f, qacc = 0.f;   // per (ch = t&63, strip = t>>6): 16 edges each
  const int ch = t & 63, strip = t >> 6;
  int buf = 0;

  for (int tile = blockIdx.x; tile < NTILES; tile += gridDim.x){
    size_t e0 = (size_t)tile * 64;

    CP_WAIT0();
    if (which==1 && t < 64) nsm[t] = d_node[e0 + t];
    __syncthreads();    // A tile (buf) + nsm ready

    // ---- prefetch NEXT tile into the other buffer (overlaps mma + epilogue) --------
    {
      int nxt = tile + gridDim.x;
      if (nxt < NTILES){
        const __half* g = hin + ((size_t)nxt*64 + e_ld)*HID + q_ld*16;
        uint sa = buf ? a_s0 : a_s1;
        cp_async16(sa, g); cp_async16(sa + 16, g + 8);
      }
      CP_COMMIT();
    }

    // ---- wmma mainloop: acc[nt] += A_kk * (Whi + Wlo) -------------------------------
    wmma::fragment<wmma::accumulator,16,16,16,float> acc[2];
    wmma::fill_fragment(acc[0], 0.f);
    wmma::fill_fragment(acc[1], 0.f);
    #pragma unroll
    for (int kk=0; kk<4; kk++){
      wmma::fragment<wmma::matrix_a,16,16,16,__half,wmma::row_major> af;
      wmma::load_matrix_sync(af, &Ash[buf][eg*16][kk*16], 72);
      #pragma unroll
      for (int nt=0; nt<2; nt++){
        wmma::mma_sync(acc[nt], af, bh[nt][kk], acc[nt]);
        wmma::mma_sync(acc[nt], af, bl[nt][kk], acc[nt]);
      }
    }
    wmma::store_matrix_sync(&stage[eg*16][nh*32 +  0], acc[0], 72, wmma::mem_row_major);
    wmma::store_matrix_sync(&stage[eg*16][nh*32 + 16], acc[1], 72, wmma::mem_row_major);
    __syncthreads();

    // ---- SINGLE-PASS epilogue: bias + relu + stats (+ store / seg-max) --------------
    {
      float bias = bsm[ch];
      float ss=0.f, qq=0.f;
      if (which==0){
        // direct column-wise fp16 store: per e, 64 lanes write 128B contiguous
        __half* hcol = hout + e0*HID + ch;
        #pragma unroll 4
        for (int e=strip*16; e<strip*16+16; e++){
          float v = fmaxf(stage[e][ch] + bias, 0.f);
          ss += v; qq += v*v;
          hcol[(size_t)e*HID] = __float2half_rn(v);
        }
      } else {
        int curn = -1; float cm = 0.f;
        #pragma unroll 4
        for (int e=strip*16; e<strip*16+16; e++){
          float v = fmaxf(stage[e][ch] + bias, 0.f);
          ss += v; qq += v*v;
          int n = nsm[e];
          if (n != curn){
            if (curn >= 0) atomicMax(&outi[(size_t)curn*HID + ch], __float_as_int(cm));
            curn = n; cm = v;
          } else {
            cm = fmaxf(cm, v);
          }
        }
        atomicMax(&outi[(size_t)curn*HID + ch], __float_as_int(cm));
      }
      sacc += ss; qacc += qq;
    }
    __syncthreads();   // stage free for next iteration
    buf ^= 1;
  }

  // flush per-channel stats (4 partials per channel per block)
  atomicAdd(&gs[ch], sacc);
  atomicAdd(&gq[ch], qacc);
}

// ---------------- finish: BN3 affine on maxes, zero for empty nodes ----------------
__global__ void k_finish(float* __restrict__ out){
  __shared__ float a[HID], c[HID];
  if (threadIdx.x < HID){ a[threadIdx.x] = d_a3[threadIdx.x]; c[threadIdx.x] = d_c3[threadIdx.x]; }
  __syncthreads();
  int idx = blockIdx.x*blockDim.x + threadIdx.x;
  int stride = gridDim.x*blockDim.x;
  for (int i = idx; i < NN*HID; i += stride){
    int ch = i & (HID-1);
    int bits = ((const int*)out)[i];
    float v = __int_as_float(bits);
    out[i] = (bits == (int)NEG_INF_BITS) ? 0.f : fmaf(a[ch], v, c[ch]);
  }
}

// ---------------- launch ------------------------------------------------------------
extern "C" void kernel_launch(void* const* d_in, const int* in_sizes, int n_in,
                              void* d_out, int out_size){
  const float*     x   = (const float*)d_in[0];
  const float*     pos = (const float*)d_in[1];
  const void*      ei  = d_in[2];
  const float* W1=(const float*)d_in[3];  const float* b1=(const float*)d_in[4];
  const float* g1=(const float*)d_in[5];  const float* be1=(const float*)d_in[6];
  const float* W2=(const float*)d_in[7];  const float* b2=(const float*)d_in[8];
  const float* g2=(const float*)d_in[9];  const float* be2=(const float*)d_in[10];
  const float* W3=(const float*)d_in[11]; const float* b3=(const float*)d_in[12];
  const float* g3=(const float*)d_in[13]; const float* be3=(const float*)d_in[14];
  float* out = (float*)d_out;
  (void)in_sizes; (void)n_in; (void)out_size;

  k_init<<<2048,256>>>((int*)out);
  k_detect<<<1024,256>>>((const long long*)ei);
  k_cvt_norm_hist<<<2048,256>>>(ei, pos);
  k_scan1<<<NBLK,1024>>>();
  k_scan2<<<1,128>>>();
  k_scan3<<<NBLK,1024>>>();
  k_layer1<<<6250,256>>>(pos, x, W1, b1);
  k_fold<<<1,64>>>(W2, b2, g1, be1, 0);
  k_layer_mma<<<MMA_GRID,256>>>(0, (int*)out);
  k_fold<<<1,64>>>(W3, b3, g2, be2, 1);
  k_layer_mma<<<MMA_GRID,256>>>(1, (int*)out);
  k_affine3<<<1,64>>>(g3, be3);
  k_finish<<<2048,256>>>(out);
}